// round 15
// baseline (speedup 1.0000x reference)
#include <cuda_runtime.h>

// Inverse discrete Hough transform, round 15 = round 14 (4x16 tile,
// pattern-sorted group gather) with:
//  - channel-half kernel split, interleaved B0->A0->B1->A1: pBT is ONE
//    reused 33.5MB buffer, so accT(73.7MB)+pBT(33.5MB)=107MB < 126MB L2
//    -> fold reads hit L2, accT stops thrashing (R14 working set was 141MB)
//  - U-bump (K=1: U=6, K=2: U=3) within the existing 24-reg buffer peak
// Pass B: angles 0..44 & 135..179, strips along y -> pBT[x*256+y][64]
// Pass A: angles 45..134, strips along x, += pBT fold, -> out (its half).

#define NA 180
#define NR 400
#define NC 256
#define OH 256
#define OW 256
#define AR (NA * NR)      // 72000
#define HW (OH * OW)      // 65536
#define NS4 16384         // strips of 4 px per pass
#define TS 96             // u32 per strip table: 4 (cum counts) + 90 offs + pad

typedef unsigned long long ull;

__device__ float  g_accT[AR * NC];                 // 73.7 MB: [a*400+r][nc]
__device__ float2 g_trig[NA];
__device__ unsigned g_tabA[(size_t)NS4 * TS];      // sorted per-strip tables
__device__ unsigned g_tabB[(size_t)NS4 * TS];
__device__ ull    g_pBT[(size_t)HW * 64];          // 33.5MB, reused per half

__device__ __forceinline__ ull fadd2(ull a, ull b) {
    ull r;
    asm("add.rn.f32x2 %0, %1, %2;" : "=l"(r) : "l"(a), "l"(b));
    return r;
}
__device__ __forceinline__ float u64lo(ull u) {
    float a, b; asm("mov.b64 {%0,%1}, %2;" : "=f"(a), "=f"(b) : "l"(u)); return a;
}
__device__ __forceinline__ float u64hi(ull u) {
    float a, b; asm("mov.b64 {%0,%1}, %2;" : "=f"(a), "=f"(b) : "l"(u)); return b;
}
#define LDG2(v0, v1, addr)                                             \
    asm("ld.global.nc.v2.u64 {%0,%1}, [%2];"                           \
        : "=l"(v0), "=l"(v1) : "l"(addr))

__global__ void k_trig() {
    int a = threadIdx.x;
    if (a < NA) {
        // f32 theta (rn multiply), then correctly-rounded f32 cos/sin via
        // double (immune to fast-math; matches the JAX reference bit-exactly).
        float t = __fmul_rn((float)a, (float)(3.14159265358979323846 / 180.0));
        double td = (double)t;
        g_trig[a] = make_float2((float)cos(td), (float)sin(td));
    }
}

// 32x32 tiled transpose of acc[256][72000] -> g_accT[72000][256]
__global__ void k_transpose(const float* __restrict__ in) {
    __shared__ float tile[32][33];
    int tx = threadIdx.x, ty = threadIdx.y;           // 32 x 8
    int ar = blockIdx.x * 32 + tx;
#pragma unroll
    for (int k = 0; k < 4; k++)
        tile[ty + k * 8][tx] = in[(size_t)(blockIdx.y * 32 + ty + k * 8) * AR + ar];
    __syncthreads();
    int nc2 = blockIdx.y * 32 + tx;
#pragma unroll
    for (int k = 0; k < 4; k++)
        g_accT[(size_t)(blockIdx.x * 32 + ty + k * 8) * NC + nc2] = tile[tx][ty + k * 8];
}

// Table builder (both passes; pass = blockIdx.y). One warp per strip:
// exact offsets, pattern code (0 flat; 1..7 asc; 9..15 desc), then the 90
// base offsets sorted by code + 16 cumulative u8 counts.
__global__ void k_tab() {
    int pass = blockIdx.y;               // 0 = A (x-strips), 1 = B (y-strips)
    int tid = threadIdx.x, w = tid >> 5, l = tid & 31;
    int s = blockIdx.x * 8 + w;
    unsigned* tabw = ((pass == 0) ? g_tabA : g_tabB) + (size_t)s * TS;
    int line = s >> 6, q0 = (s & 63) << 2;

    unsigned codev[3], basev[3];
#pragma unroll
    for (int i = 0; i < 3; i++) {
        int ar = i * 32 + l;
        codev[i] = 0xFFFFu;
        if (ar < 90) {
            int a = (pass == 0) ? (45 + ar) : (ar < 45 ? ar : ar + 90);
            float2 cs = g_trig[a];
            unsigned off[4];
#pragma unroll
            for (int p = 0; p < 4; p++) {
                int x = (pass == 0) ? (q0 + p) : line;
                int y = (pass == 0) ? line : (q0 + p);
                // exact reference arithmetic: rn(rn(xc*c)+rn(yc*s)), rne round
                float sum = __fadd_rn(__fmul_rn((float)(x - 128), cs.x),
                                      __fmul_rn((float)(y - 128), cs.y));
                off[p] = (unsigned)(a * NR + __float2int_rn(sum) + 200) << 10;
            }
            int d1 = ((int)(off[1] - off[0])) >> 10;
            int d2 = ((int)(off[2] - off[0])) >> 10;
            int d3 = ((int)(off[3] - off[0])) >> 10;
            int b1 = d1 != 0, b2 = d2 != d1, b3 = d3 != d2;
            int bits = b1 | (b2 << 1) | (b3 << 2);
            int neg = (d1 < 0) | (d2 < 0) | (d3 < 0);
            codev[i] = (bits == 0) ? 0u : (unsigned)(bits + (neg ? 8 : 0));
            basev[i] = off[0];
        }
    }

    unsigned lmlt = (1u << l) - 1u;
    int cnt = 0;
    unsigned cword[4] = {0, 0, 0, 0};
#pragma unroll
    for (int c = 0; c < 16; c++) {
#pragma unroll
        for (int i = 0; i < 3; i++) {
            bool v = (codev[i] == (unsigned)c);
            unsigned m = __ballot_sync(0xFFFFFFFFu, v);
            if (v) tabw[4 + cnt + __popc(m & lmlt)] = basev[i];
            cnt += __popc(m);
        }
        cword[c >> 2] |= (unsigned)cnt << ((c & 3) * 8);
    }
    if (l == 0) {
        tabw[0] = cword[0]; tabw[1] = cword[1];
        tabw[2] = cword[2]; tabw[3] = cword[3];
    }
}

// loads for one angle (half-channel): K rows, 1 LDG.128-pair (16B/lane) each
template <int K, int S>
__device__ __forceinline__ void angle_loads(ull addr, ull (*r)[2]) {
#pragma unroll
    for (int j = 0; j < K; j++)
        LDG2(r[j][0], r[j][1], addr + S * 1024 * j);
}
// adds for one angle: pixel p uses row {0,P1,P2,P3}[p]; 8 packed rn adds
template <int K, int P1, int P2, int P3>
__device__ __forceinline__ void angle_adds(ull (*r)[2], ull* acc) {
    acc[0] = fadd2(acc[0], r[0][0]);  acc[1] = fadd2(acc[1], r[0][1]);
    acc[2] = fadd2(acc[2], r[P1][0]); acc[3] = fadd2(acc[3], r[P1][1]);
    acc[4] = fadd2(acc[4], r[P2][0]); acc[5] = fadd2(acc[5], r[P2][1]);
    acc[6] = fadd2(acc[6], r[P3][0]); acc[7] = fadd2(acc[7], r[P3][1]);
}

// One pattern group, U angles per iteration: all U angle-loads issued
// before any dependent add -> U*K independent LDG.128 in flight.
template <int K, int S, int P1, int P2, int P3, int U>
__device__ __forceinline__ void run_group(int n, const unsigned* toff,
                                          int& idx, ull base, ull* acc) {
    int i = 0;
    for (; i + U <= n; i += U) {
        unsigned offs[U];
#pragma unroll
        for (int u = 0; u < U; u++) offs[u] = toff[idx + i + u];
        ull r[U][K][2];
#pragma unroll
        for (int u = 0; u < U; u++) angle_loads<K, S>(base + offs[u], r[u]);
#pragma unroll
        for (int u = 0; u < U; u++) angle_adds<K, P1, P2, P3>(r[u], acc);
    }
    for (; i < n; i++) {
        ull r[K][2];
        angle_loads<K, S>(base + toff[idx + i], r);
        angle_adds<K, P1, P2, P3>(r, acc);
    }
    idx += n;
}

// Main pass, ONE channel half (runtime arg). CTA = 512 threads = 16 warps =
// 16 strips (4 lines x 4 positions); warp = 4 px x 128 ch (lane = 16B slice).
template <int PASS>
__global__ __launch_bounds__(512, 2) void k_pass(float* __restrict__ outp,
                                                 int half) {
    __shared__ union SM {
        unsigned tw[16 * TS];        // 16 strip tables (6 KB)
        float stage[32 * 136];       // epilogue: 32 px x 128 ch (two rounds)
    } sm;

    const unsigned* tab = (PASS == 0) ? g_tabA : g_tabB;
    int tid = threadIdx.x, w = tid >> 5, l = tid & 31;
    int dl = w & 3, dq = w >> 2;               // line 0..3, position 0..3
    int jj = blockIdx.x >> 4, kk = blockIdx.x & 15;
    int line = 4 * jj + dl;
    int pos = 4 * kk + dq;
    int q0 = pos << 2;
    int s = line * 64 + pos;

    if (l < 24)
        ((uint4*)(sm.tw + w * TS))[l] =
            __ldg((const uint4*)(tab + (size_t)s * TS) + l);
    __syncthreads();

    const unsigned* tw = sm.tw + w * TS;
    const unsigned char* cb = (const unsigned char*)tw;   // cumulative counts
    const unsigned* toff = tw + 4;

    ull base;
    {
        const char* gp = (const char*)g_accT + half * 512 + l * 16;
        asm("cvta.to.global.u64 %0, %1;" : "=l"(base) : "l"(gp));
    }

    // acc[2p+q]: pixel p, channels half*128 + l*4 + 2q .. +2q+1
    ull acc[8];
#pragma unroll
    for (int i = 0; i < 8; i++) acc[i] = 0ull;

    int idx = 0;
#define GC(c) ((int)cb[c] - ((c) ? (int)cb[(c)-1] : 0))
    run_group<1,  1, 0, 0, 0, 6>(GC(0),  toff, idx, base, acc);
    run_group<2,  1, 1, 1, 1, 3>(GC(1),  toff, idx, base, acc);
    run_group<2,  1, 0, 1, 1, 3>(GC(2),  toff, idx, base, acc);
    run_group<3,  1, 1, 2, 2, 2>(GC(3),  toff, idx, base, acc);
    run_group<2,  1, 0, 0, 1, 3>(GC(4),  toff, idx, base, acc);
    run_group<3,  1, 1, 1, 2, 2>(GC(5),  toff, idx, base, acc);
    run_group<3,  1, 0, 1, 2, 2>(GC(6),  toff, idx, base, acc);
    run_group<4,  1, 1, 2, 3, 1>(GC(7),  toff, idx, base, acc);
    // code 8 impossible (flat+neg)
    run_group<2, -1, 1, 1, 1, 3>(GC(9),  toff, idx, base, acc);
    run_group<2, -1, 0, 1, 1, 3>(GC(10), toff, idx, base, acc);
    run_group<3, -1, 1, 2, 2, 2>(GC(11), toff, idx, base, acc);
    run_group<2, -1, 0, 0, 1, 3>(GC(12), toff, idx, base, acc);
    run_group<3, -1, 1, 1, 2, 2>(GC(13), toff, idx, base, acc);
    run_group<3, -1, 0, 1, 2, 2>(GC(14), toff, idx, base, acc);
    run_group<4, -1, 1, 2, 3, 1>(GC(15), toff, idx, base, acc);
#undef GC

    if (PASS == 1) {
        // pixel-major staging: pix = x*256 + y = line*256 + q0 + p
#pragma unroll
        for (int p = 0; p < 4; p++) {
            ull* pw = g_pBT + ((size_t)line * 256 + q0 + p) * 64;
            *reinterpret_cast<ulonglong2*>(pw + l * 2) =
                make_ulonglong2(acc[2 * p], acc[2 * p + 1]);
        }
        return;
    }

    // PASS A: fold pass-B partials; pixel (x=q0+p, y=line) -> pix = x*256+y
#pragma unroll
    for (int p = 0; p < 4; p++) {
        const ull* pr = g_pBT + ((size_t)(q0 + p) * 256 + line) * 64;
        ulonglong2 b = __ldg(reinterpret_cast<const ulonglong2*>(pr + l * 2));
        acc[2 * p]     = fadd2(acc[2 * p],     b.x);
        acc[2 * p + 1] = fadd2(acc[2 * p + 1], b.y);
    }

    // epilogue in two rounds of 2 lines (32 px x 128 ch); re-read channel-
    // major, store 16 contiguous x per line per channel
    int c2 = tid & 127, u = tid >> 7;          // u = 0..3
#pragma unroll
    for (int h = 0; h < 2; h++) {
        __syncthreads();   // round 0: also protects the table/stage union
        if ((dl >> 1) == h) {
#pragma unroll
            for (int p = 0; p < 4; p++) {
                float* st = sm.stage + (size_t)((dl & 1) * 16 + dq * 4 + p) * 136
                          + l * 4;
                *reinterpret_cast<float4*>(st) =
                    make_float4(u64lo(acc[2 * p]),     u64hi(acc[2 * p]),
                                u64lo(acc[2 * p + 1]), u64hi(acc[2 * p + 1]));
            }
        }
        __syncthreads();
        // thread (c2, u): line = 2h + (u&1), x-half = (u>>1)*8
        int LL = 4 * jj + 2 * h + (u & 1);
        int xo = (u >> 1) * 8;
        float* op = outp + (size_t)(half * 128 + c2) * HW + LL * 256
                  + 16 * kk + xo;
#pragma unroll
        for (int g = 0; g < 2; g++) {
            int pb = (u & 1) * 16 + xo + 4 * g;
            float4 q = make_float4(sm.stage[(size_t)(pb + 0) * 136 + c2],
                                   sm.stage[(size_t)(pb + 1) * 136 + c2],
                                   sm.stage[(size_t)(pb + 2) * 136 + c2],
                                   sm.stage[(size_t)(pb + 3) * 136 + c2]);
            *reinterpret_cast<float4*>(op + 4 * g) = q;
        }
    }
}

extern "C" void kernel_launch(void* const* d_in, const int* in_sizes, int n_in,
                              void* d_out, int out_size) {
    const float* acc = (const float*)d_in[0];
    float* out = (float*)d_out;

    k_trig<<<1, 192>>>();
    k_transpose<<<dim3(AR / 32, NC / 32), dim3(32, 8)>>>(acc);
    k_tab<<<dim3(NS4 / 8, 2), 256>>>();       // both sorted tables, one launch
    // interleaved per channel half: pBT buffer reused, stays L2-resident
    k_pass<1><<<1024, 512>>>(out, 0);         // B half0 -> pBT
    k_pass<0><<<1024, 512>>>(out, 0);         // A half0: += pBT, -> out
    k_pass<1><<<1024, 512>>>(out, 1);         // B half1 -> pBT
    k_pass<0><<<1024, 512>>>(out, 1);         // A half1: += pBT, -> out
}

// round 16
// speedup vs baseline: 1.0769x; 1.0769x over previous
#include <cuda_runtime.h>

// Inverse discrete Hough transform, round 16: FUSED single-pass kernel.
// 8x8 pixel tile per 1024-thread CTA. 32 warps = 16 x-strips x 2 channel
// halves for angles 45..134 (phase A), then an in-SMEM partial exchange
// re-maps the same warps to 16 y-strips x 2 halves for angles 0..44 &
// 135..179 (phase B). pBT staging buffer is GONE: working set = accT only
// (73.7MB, L2-resident), one kernel instead of two.
// Gather core (pattern-sorted group loops), tables, k_tab, trig, transpose
// are byte-identical to R14 (proven at rel_err 2.8e-7).

#define NA 180
#define NR 400
#define NC 256
#define OH 256
#define OW 256
#define AR (NA * NR)      // 72000
#define HW (OH * OW)      // 65536
#define NS4 16384         // strips of 4 px per orientation
#define TS 96             // u32 per strip table: 4 (cum counts) + 90 offs + pad

typedef unsigned long long ull;

__device__ float  g_accT[AR * NC];                 // 73.7 MB: [a*400+r][nc]
__device__ float2 g_trig[NA];
__device__ unsigned g_tabA[(size_t)NS4 * TS];      // sorted per-strip tables
__device__ unsigned g_tabB[(size_t)NS4 * TS];

__device__ __forceinline__ ull fadd2(ull a, ull b) {
    ull r;
    asm("add.rn.f32x2 %0, %1, %2;" : "=l"(r) : "l"(a), "l"(b));
    return r;
}
__device__ __forceinline__ float u64lo(ull u) {
    float a, b; asm("mov.b64 {%0,%1}, %2;" : "=f"(a), "=f"(b) : "l"(u)); return a;
}
__device__ __forceinline__ float u64hi(ull u) {
    float a, b; asm("mov.b64 {%0,%1}, %2;" : "=f"(a), "=f"(b) : "l"(u)); return b;
}
__device__ __forceinline__ ull pack2(float lo, float hi) {
    ull r; asm("mov.b64 %0, {%1,%2};" : "=l"(r) : "f"(lo), "f"(hi)); return r;
}
#define LDG2(v0, v1, addr)                                             \
    asm("ld.global.nc.v2.u64 {%0,%1}, [%2];"                           \
        : "=l"(v0), "=l"(v1) : "l"(addr))

__global__ void k_trig() {
    int a = threadIdx.x;
    if (a < NA) {
        // f32 theta (rn multiply), then correctly-rounded f32 cos/sin via
        // double (immune to fast-math; matches the JAX reference bit-exactly).
        float t = __fmul_rn((float)a, (float)(3.14159265358979323846 / 180.0));
        double td = (double)t;
        g_trig[a] = make_float2((float)cos(td), (float)sin(td));
    }
}

// 32x32 tiled transpose of acc[256][72000] -> g_accT[72000][256]
__global__ void k_transpose(const float* __restrict__ in) {
    __shared__ float tile[32][33];
    int tx = threadIdx.x, ty = threadIdx.y;           // 32 x 8
    int ar = blockIdx.x * 32 + tx;
#pragma unroll
    for (int k = 0; k < 4; k++)
        tile[ty + k * 8][tx] = in[(size_t)(blockIdx.y * 32 + ty + k * 8) * AR + ar];
    __syncthreads();
    int nc2 = blockIdx.y * 32 + tx;
#pragma unroll
    for (int k = 0; k < 4; k++)
        g_accT[(size_t)(blockIdx.x * 32 + ty + k * 8) * NC + nc2] = tile[tx][ty + k * 8];
}

// Table builder (both orientations; pass = blockIdx.y). One warp per strip:
// exact offsets, pattern code (0 flat; 1..7 asc; 9..15 desc), then the 90
// base offsets sorted by code + 16 cumulative u8 counts.
__global__ void k_tab() {
    int pass = blockIdx.y;               // 0 = A (x-strips), 1 = B (y-strips)
    int tid = threadIdx.x, w = tid >> 5, l = tid & 31;
    int s = blockIdx.x * 8 + w;
    unsigned* tabw = ((pass == 0) ? g_tabA : g_tabB) + (size_t)s * TS;
    int line = s >> 6, q0 = (s & 63) << 2;

    unsigned codev[3], basev[3];
#pragma unroll
    for (int i = 0; i < 3; i++) {
        int ar = i * 32 + l;
        codev[i] = 0xFFFFu;
        if (ar < 90) {
            int a = (pass == 0) ? (45 + ar) : (ar < 45 ? ar : ar + 90);
            float2 cs = g_trig[a];
            unsigned off[4];
#pragma unroll
            for (int p = 0; p < 4; p++) {
                int x = (pass == 0) ? (q0 + p) : line;
                int y = (pass == 0) ? line : (q0 + p);
                // exact reference arithmetic: rn(rn(xc*c)+rn(yc*s)), rne round
                float sum = __fadd_rn(__fmul_rn((float)(x - 128), cs.x),
                                      __fmul_rn((float)(y - 128), cs.y));
                off[p] = (unsigned)(a * NR + __float2int_rn(sum) + 200) << 10;
            }
            int d1 = ((int)(off[1] - off[0])) >> 10;
            int d2 = ((int)(off[2] - off[0])) >> 10;
            int d3 = ((int)(off[3] - off[0])) >> 10;
            int b1 = d1 != 0, b2 = d2 != d1, b3 = d3 != d2;
            int bits = b1 | (b2 << 1) | (b3 << 2);
            int neg = (d1 < 0) | (d2 < 0) | (d3 < 0);
            codev[i] = (bits == 0) ? 0u : (unsigned)(bits + (neg ? 8 : 0));
            basev[i] = off[0];
        }
    }

    unsigned lmlt = (1u << l) - 1u;
    int cnt = 0;
    unsigned cword[4] = {0, 0, 0, 0};
#pragma unroll
    for (int c = 0; c < 16; c++) {
#pragma unroll
        for (int i = 0; i < 3; i++) {
            bool v = (codev[i] == (unsigned)c);
            unsigned m = __ballot_sync(0xFFFFFFFFu, v);
            if (v) tabw[4 + cnt + __popc(m & lmlt)] = basev[i];
            cnt += __popc(m);
        }
        cword[c >> 2] |= (unsigned)cnt << ((c & 3) * 8);
    }
    if (l == 0) {
        tabw[0] = cword[0]; tabw[1] = cword[1];
        tabw[2] = cword[2]; tabw[3] = cword[3];
    }
}

// loads for one angle (half-channel): K rows, 1 LDG.128-pair (16B/lane) each
template <int K, int S>
__device__ __forceinline__ void angle_loads(ull addr, ull (*r)[2]) {
#pragma unroll
    for (int j = 0; j < K; j++)
        LDG2(r[j][0], r[j][1], addr + S * 1024 * j);
}
// adds for one angle: pixel p uses row {0,P1,P2,P3}[p]; 8 packed rn adds
template <int K, int P1, int P2, int P3>
__device__ __forceinline__ void angle_adds(ull (*r)[2], ull* acc) {
    acc[0] = fadd2(acc[0], r[0][0]);  acc[1] = fadd2(acc[1], r[0][1]);
    acc[2] = fadd2(acc[2], r[P1][0]); acc[3] = fadd2(acc[3], r[P1][1]);
    acc[4] = fadd2(acc[4], r[P2][0]); acc[5] = fadd2(acc[5], r[P2][1]);
    acc[6] = fadd2(acc[6], r[P3][0]); acc[7] = fadd2(acc[7], r[P3][1]);
}

// One pattern group, U angles per iteration: all U angle-loads issued
// before any dependent add -> U*K independent LDG.128 in flight.
template <int K, int S, int P1, int P2, int P3, int U>
__device__ __forceinline__ void run_group(int n, const unsigned* toff,
                                          int& idx, ull base, ull* acc) {
    int i = 0;
    for (; i + U <= n; i += U) {
        unsigned offs[U];
#pragma unroll
        for (int u = 0; u < U; u++) offs[u] = toff[idx + i + u];
        ull r[U][K][2];
#pragma unroll
        for (int u = 0; u < U; u++) angle_loads<K, S>(base + offs[u], r[u]);
#pragma unroll
        for (int u = 0; u < U; u++) angle_adds<K, P1, P2, P3>(r[u], acc);
    }
    for (; i < n; i++) {
        ull r[K][2];
        angle_loads<K, S>(base + toff[idx + i], r);
        angle_adds<K, P1, P2, P3>(r, acc);
    }
    idx += n;
}

// all 15 pattern groups for one strip table (R14 U values)
__device__ __forceinline__ void gather90(const unsigned* tw, ull base, ull* acc) {
    const unsigned char* cb = (const unsigned char*)tw;   // cumulative counts
    const unsigned* toff = tw + 4;
    int idx = 0;
#define GC(c) ((int)cb[c] - ((c) ? (int)cb[(c)-1] : 0))
    run_group<1,  1, 0, 0, 0, 4>(GC(0),  toff, idx, base, acc);
    run_group<2,  1, 1, 1, 1, 2>(GC(1),  toff, idx, base, acc);
    run_group<2,  1, 0, 1, 1, 2>(GC(2),  toff, idx, base, acc);
    run_group<3,  1, 1, 2, 2, 2>(GC(3),  toff, idx, base, acc);
    run_group<2,  1, 0, 0, 1, 2>(GC(4),  toff, idx, base, acc);
    run_group<3,  1, 1, 1, 2, 2>(GC(5),  toff, idx, base, acc);
    run_group<3,  1, 0, 1, 2, 2>(GC(6),  toff, idx, base, acc);
    run_group<4,  1, 1, 2, 3, 1>(GC(7),  toff, idx, base, acc);
    // code 8 impossible (flat+neg)
    run_group<2, -1, 1, 1, 1, 2>(GC(9),  toff, idx, base, acc);
    run_group<2, -1, 0, 1, 1, 2>(GC(10), toff, idx, base, acc);
    run_group<3, -1, 1, 2, 2, 2>(GC(11), toff, idx, base, acc);
    run_group<2, -1, 0, 0, 1, 2>(GC(12), toff, idx, base, acc);
    run_group<3, -1, 1, 1, 2, 2>(GC(13), toff, idx, base, acc);
    run_group<3, -1, 0, 1, 2, 2>(GC(14), toff, idx, base, acc);
    run_group<4, -1, 1, 2, 3, 1>(GC(15), toff, idx, base, acc);
#undef GC
}

// Fused kernel. CTA = 1024 thr = 32 warps = 16 strips x 2 halves, tile 8x8 px.
// Dynamic SMEM: 32 strip tables (12.3KB) + stage[2][64][132] f32 (67.6KB).
#define SM_STAGE_OFF (32 * TS)                       // u32 offset of stage
#define SMEM_FUSED   ((32 * TS + 2 * 64 * 132) * 4)  // 79872 bytes

__global__ __launch_bounds__(1024, 1) void k_fused(float* __restrict__ outp) {
    extern __shared__ unsigned dsm[];
    unsigned* tabs = dsm;
    float* stage = (float*)(dsm + SM_STAGE_OFF);

    int tid = threadIdx.x, w = tid >> 5, l = tid & 31;
    int half = w & 1, t = w >> 1;                    // strip slot 0..15
    int by = blockIdx.x >> 5, bx = blockIdx.x & 31;
    int x0 = bx * 8, y0 = by * 8;

    // load 32 tables: tb<16 -> A strip (dl=tb&7, dq=tb>>3);
    //                 tb>=16 -> B strip (dc, dqy) likewise
    if (tid < 768) {
        int tb = tid / 24, e = tid % 24;
        int sIdx;
        const unsigned* src;
        if (tb < 16) { sIdx = (y0 + (tb & 7)) * 64 + bx * 2 + (tb >> 3); src = g_tabA; }
        else { int b2 = tb - 16; sIdx = (x0 + (b2 & 7)) * 64 + by * 2 + (b2 >> 3); src = g_tabB; }
        ((uint4*)(tabs + tb * TS))[e] =
            __ldg((const uint4*)(src + (size_t)sIdx * TS) + e);
    }
    __syncthreads();

    ull base;
    {
        const char* gp = (const char*)g_accT + half * 512 + l * 16;
        asm("cvta.to.global.u64 %0, %1;" : "=l"(base) : "l"(gp));
    }
    float* reg = stage + half * (64 * 132);

    // ---- phase A: x-strip (line y0+dl, x = x0 + dq*4 + p) ----
    {
        int dl = t & 7, dq = t >> 3;
        ull acc[8];
#pragma unroll
        for (int i = 0; i < 8; i++) acc[i] = 0ull;
        gather90(tabs + t * TS, base, acc);
        // stage A partials: local_px = (y-local)*8 + (x-local)
#pragma unroll
        for (int p = 0; p < 4; p++) {
            float* st = reg + (size_t)(dl * 8 + dq * 4 + p) * 132 + l * 4;
            *reinterpret_cast<float4*>(st) =
                make_float4(u64lo(acc[2 * p]),     u64hi(acc[2 * p]),
                            u64lo(acc[2 * p + 1]), u64hi(acc[2 * p + 1]));
        }
    }
    __syncthreads();

    // ---- phase B: y-strip (column x0+dc, y = y0 + dqy*4 + p) ----
    int dc = t & 7, dqy = t >> 3;
    ull acc[8];
#pragma unroll
    for (int p = 0; p < 4; p++) {           // init from A partials
        const float* st = reg + (size_t)((dqy * 4 + p) * 8 + dc) * 132 + l * 4;
        float4 q = *reinterpret_cast<const float4*>(st);
        acc[2 * p]     = pack2(q.x, q.y);
        acc[2 * p + 1] = pack2(q.z, q.w);
    }
    __syncthreads();                         // reads done before re-staging

    gather90(tabs + (16 + t) * TS, base, acc);

    __syncthreads();
#pragma unroll
    for (int p = 0; p < 4; p++) {            // stage final values
        float* st = reg + (size_t)((dqy * 4 + p) * 8 + dc) * 132 + l * 4;
        *reinterpret_cast<float4*>(st) =
            make_float4(u64lo(acc[2 * p]),     u64hi(acc[2 * p]),
                        u64lo(acc[2 * p + 1]), u64hi(acc[2 * p + 1]));
    }
    __syncthreads();

    // ---- epilogue: thread (c = tid&255, u = tid>>8) stores lines 2u, 2u+1 ----
    {
        int c = tid & 255, u = tid >> 8;
        int h2 = c >> 7, c2 = c & 127;
        const float* rg = stage + h2 * (64 * 132);
#pragma unroll
        for (int dl2 = 0; dl2 < 2; dl2++) {
            int LL = u * 2 + dl2;
            float* op = outp + (size_t)c * HW + (y0 + LL) * 256 + x0;
#pragma unroll
            for (int g = 0; g < 2; g++) {
                int pb = LL * 8 + 4 * g;
                float4 q = make_float4(rg[(size_t)(pb + 0) * 132 + c2],
                                       rg[(size_t)(pb + 1) * 132 + c2],
                                       rg[(size_t)(pb + 2) * 132 + c2],
                                       rg[(size_t)(pb + 3) * 132 + c2]);
                *reinterpret_cast<float4*>(op + 4 * g) = q;
            }
        }
    }
}

extern "C" void kernel_launch(void* const* d_in, const int* in_sizes, int n_in,
                              void* d_out, int out_size) {
    const float* acc = (const float*)d_in[0];
    float* out = (float*)d_out;

    cudaFuncSetAttribute(k_fused, cudaFuncAttributeMaxDynamicSharedMemorySize,
                         SMEM_FUSED);

    k_trig<<<1, 192>>>();
    k_transpose<<<dim3(AR / 32, NC / 32), dim3(32, 8)>>>(acc);
    k_tab<<<dim3(NS4 / 8, 2), 256>>>();       // both sorted tables, one launch
    k_fused<<<1024, 1024, SMEM_FUSED>>>(out); // A + exchange + B + store
}

// round 17
// speedup vs baseline: 1.0791x; 1.0021x over previous
#include <cuda_runtime.h>

// Inverse discrete Hough transform, round 17 = round 16 (fused single-pass,
// 8x8 tile, pattern-sorted group gather) with two additive levers:
//  - U-bump: K=1 groups U=6, K=2 groups U=3 (peak row-buffer 24 regs, same
//    as the existing K=3/U=2 peak -> no register growth expected)
//  - 2D CTA swizzle: groups of 16 CTAs cover 4x4 tile squares, so
//    concurrently-resident CTAs share rho rows in BOTH strip orientations
//    -> L2 traffic down, average gather latency down.

#define NA 180
#define NR 400
#define NC 256
#define OH 256
#define OW 256
#define AR (NA * NR)      // 72000
#define HW (OH * OW)      // 65536
#define NS4 16384         // strips of 4 px per orientation
#define TS 96             // u32 per strip table: 4 (cum counts) + 90 offs + pad

typedef unsigned long long ull;

__device__ float  g_accT[AR * NC];                 // 73.7 MB: [a*400+r][nc]
__device__ float2 g_trig[NA];
__device__ unsigned g_tabA[(size_t)NS4 * TS];      // sorted per-strip tables
__device__ unsigned g_tabB[(size_t)NS4 * TS];

__device__ __forceinline__ ull fadd2(ull a, ull b) {
    ull r;
    asm("add.rn.f32x2 %0, %1, %2;" : "=l"(r) : "l"(a), "l"(b));
    return r;
}
__device__ __forceinline__ float u64lo(ull u) {
    float a, b; asm("mov.b64 {%0,%1}, %2;" : "=f"(a), "=f"(b) : "l"(u)); return a;
}
__device__ __forceinline__ float u64hi(ull u) {
    float a, b; asm("mov.b64 {%0,%1}, %2;" : "=f"(a), "=f"(b) : "l"(u)); return b;
}
__device__ __forceinline__ ull pack2(float lo, float hi) {
    ull r; asm("mov.b64 %0, {%1,%2};" : "=l"(r) : "f"(lo), "f"(hi)); return r;
}
#define LDG2(v0, v1, addr)                                             \
    asm("ld.global.nc.v2.u64 {%0,%1}, [%2];"                           \
        : "=l"(v0), "=l"(v1) : "l"(addr))

__global__ void k_trig() {
    int a = threadIdx.x;
    if (a < NA) {
        // f32 theta (rn multiply), then correctly-rounded f32 cos/sin via
        // double (immune to fast-math; matches the JAX reference bit-exactly).
        float t = __fmul_rn((float)a, (float)(3.14159265358979323846 / 180.0));
        double td = (double)t;
        g_trig[a] = make_float2((float)cos(td), (float)sin(td));
    }
}

// 32x32 tiled transpose of acc[256][72000] -> g_accT[72000][256]
__global__ void k_transpose(const float* __restrict__ in) {
    __shared__ float tile[32][33];
    int tx = threadIdx.x, ty = threadIdx.y;           // 32 x 8
    int ar = blockIdx.x * 32 + tx;
#pragma unroll
    for (int k = 0; k < 4; k++)
        tile[ty + k * 8][tx] = in[(size_t)(blockIdx.y * 32 + ty + k * 8) * AR + ar];
    __syncthreads();
    int nc2 = blockIdx.y * 32 + tx;
#pragma unroll
    for (int k = 0; k < 4; k++)
        g_accT[(size_t)(blockIdx.x * 32 + ty + k * 8) * NC + nc2] = tile[tx][ty + k * 8];
}

// Table builder (both orientations; pass = blockIdx.y). One warp per strip:
// exact offsets, pattern code (0 flat; 1..7 asc; 9..15 desc), then the 90
// base offsets sorted by code + 16 cumulative u8 counts.
__global__ void k_tab() {
    int pass = blockIdx.y;               // 0 = A (x-strips), 1 = B (y-strips)
    int tid = threadIdx.x, w = tid >> 5, l = tid & 31;
    int s = blockIdx.x * 8 + w;
    unsigned* tabw = ((pass == 0) ? g_tabA : g_tabB) + (size_t)s * TS;
    int line = s >> 6, q0 = (s & 63) << 2;

    unsigned codev[3], basev[3];
#pragma unroll
    for (int i = 0; i < 3; i++) {
        int ar = i * 32 + l;
        codev[i] = 0xFFFFu;
        if (ar < 90) {
            int a = (pass == 0) ? (45 + ar) : (ar < 45 ? ar : ar + 90);
            float2 cs = g_trig[a];
            unsigned off[4];
#pragma unroll
            for (int p = 0; p < 4; p++) {
                int x = (pass == 0) ? (q0 + p) : line;
                int y = (pass == 0) ? line : (q0 + p);
                // exact reference arithmetic: rn(rn(xc*c)+rn(yc*s)), rne round
                float sum = __fadd_rn(__fmul_rn((float)(x - 128), cs.x),
                                      __fmul_rn((float)(y - 128), cs.y));
                off[p] = (unsigned)(a * NR + __float2int_rn(sum) + 200) << 10;
            }
            int d1 = ((int)(off[1] - off[0])) >> 10;
            int d2 = ((int)(off[2] - off[0])) >> 10;
            int d3 = ((int)(off[3] - off[0])) >> 10;
            int b1 = d1 != 0, b2 = d2 != d1, b3 = d3 != d2;
            int bits = b1 | (b2 << 1) | (b3 << 2);
            int neg = (d1 < 0) | (d2 < 0) | (d3 < 0);
            codev[i] = (bits == 0) ? 0u : (unsigned)(bits + (neg ? 8 : 0));
            basev[i] = off[0];
        }
    }

    unsigned lmlt = (1u << l) - 1u;
    int cnt = 0;
    unsigned cword[4] = {0, 0, 0, 0};
#pragma unroll
    for (int c = 0; c < 16; c++) {
#pragma unroll
        for (int i = 0; i < 3; i++) {
            bool v = (codev[i] == (unsigned)c);
            unsigned m = __ballot_sync(0xFFFFFFFFu, v);
            if (v) tabw[4 + cnt + __popc(m & lmlt)] = basev[i];
            cnt += __popc(m);
        }
        cword[c >> 2] |= (unsigned)cnt << ((c & 3) * 8);
    }
    if (l == 0) {
        tabw[0] = cword[0]; tabw[1] = cword[1];
        tabw[2] = cword[2]; tabw[3] = cword[3];
    }
}

// loads for one angle (half-channel): K rows, 1 LDG.128-pair (16B/lane) each
template <int K, int S>
__device__ __forceinline__ void angle_loads(ull addr, ull (*r)[2]) {
#pragma unroll
    for (int j = 0; j < K; j++)
        LDG2(r[j][0], r[j][1], addr + S * 1024 * j);
}
// adds for one angle: pixel p uses row {0,P1,P2,P3}[p]; 8 packed rn adds
template <int K, int P1, int P2, int P3>
__device__ __forceinline__ void angle_adds(ull (*r)[2], ull* acc) {
    acc[0] = fadd2(acc[0], r[0][0]);  acc[1] = fadd2(acc[1], r[0][1]);
    acc[2] = fadd2(acc[2], r[P1][0]); acc[3] = fadd2(acc[3], r[P1][1]);
    acc[4] = fadd2(acc[4], r[P2][0]); acc[5] = fadd2(acc[5], r[P2][1]);
    acc[6] = fadd2(acc[6], r[P3][0]); acc[7] = fadd2(acc[7], r[P3][1]);
}

// One pattern group, U angles per iteration: all U angle-loads issued
// before any dependent add -> U*K independent LDG.128 in flight.
template <int K, int S, int P1, int P2, int P3, int U>
__device__ __forceinline__ void run_group(int n, const unsigned* toff,
                                          int& idx, ull base, ull* acc) {
    int i = 0;
    for (; i + U <= n; i += U) {
        unsigned offs[U];
#pragma unroll
        for (int u = 0; u < U; u++) offs[u] = toff[idx + i + u];
        ull r[U][K][2];
#pragma unroll
        for (int u = 0; u < U; u++) angle_loads<K, S>(base + offs[u], r[u]);
#pragma unroll
        for (int u = 0; u < U; u++) angle_adds<K, P1, P2, P3>(r[u], acc);
    }
    for (; i < n; i++) {
        ull r[K][2];
        angle_loads<K, S>(base + toff[idx + i], r);
        angle_adds<K, P1, P2, P3>(r, acc);
    }
    idx += n;
}

// all 15 pattern groups for one strip table (U-bumped: K1=6, K2=3)
__device__ __forceinline__ void gather90(const unsigned* tw, ull base, ull* acc) {
    const unsigned char* cb = (const unsigned char*)tw;   // cumulative counts
    const unsigned* toff = tw + 4;
    int idx = 0;
#define GC(c) ((int)cb[c] - ((c) ? (int)cb[(c)-1] : 0))
    run_group<1,  1, 0, 0, 0, 6>(GC(0),  toff, idx, base, acc);
    run_group<2,  1, 1, 1, 1, 3>(GC(1),  toff, idx, base, acc);
    run_group<2,  1, 0, 1, 1, 3>(GC(2),  toff, idx, base, acc);
    run_group<3,  1, 1, 2, 2, 2>(GC(3),  toff, idx, base, acc);
    run_group<2,  1, 0, 0, 1, 3>(GC(4),  toff, idx, base, acc);
    run_group<3,  1, 1, 1, 2, 2>(GC(5),  toff, idx, base, acc);
    run_group<3,  1, 0, 1, 2, 2>(GC(6),  toff, idx, base, acc);
    run_group<4,  1, 1, 2, 3, 1>(GC(7),  toff, idx, base, acc);
    // code 8 impossible (flat+neg)
    run_group<2, -1, 1, 1, 1, 3>(GC(9),  toff, idx, base, acc);
    run_group<2, -1, 0, 1, 1, 3>(GC(10), toff, idx, base, acc);
    run_group<3, -1, 1, 2, 2, 2>(GC(11), toff, idx, base, acc);
    run_group<2, -1, 0, 0, 1, 3>(GC(12), toff, idx, base, acc);
    run_group<3, -1, 1, 1, 2, 2>(GC(13), toff, idx, base, acc);
    run_group<3, -1, 0, 1, 2, 2>(GC(14), toff, idx, base, acc);
    run_group<4, -1, 1, 2, 3, 1>(GC(15), toff, idx, base, acc);
#undef GC
}

// Fused kernel. CTA = 1024 thr = 32 warps = 16 strips x 2 halves, tile 8x8 px.
// Dynamic SMEM: 32 strip tables (12.3KB) + stage[2][64][132] f32 (67.6KB).
#define SM_STAGE_OFF (32 * TS)                       // u32 offset of stage
#define SMEM_FUSED   ((32 * TS + 2 * 64 * 132) * 4)  // 79872 bytes

__global__ __launch_bounds__(1024, 1) void k_fused(float* __restrict__ outp) {
    extern __shared__ unsigned dsm[];
    unsigned* tabs = dsm;
    float* stage = (float*)(dsm + SM_STAGE_OFF);

    int tid = threadIdx.x, w = tid >> 5, l = tid & 31;
    int half = w & 1, t = w >> 1;                    // strip slot 0..15

    // 2D swizzle: 16 consecutive CTAs cover a 4x4 tile square ->
    // concurrent CTAs share rho rows in BOTH orientations
    int g = blockIdx.x >> 4, i4 = blockIdx.x & 15;   // g: 8x8 squares
    int by = (g >> 3) * 4 + (i4 >> 2);
    int bx = (g & 7) * 4 + (i4 & 3);
    int x0 = bx * 8, y0 = by * 8;

    // load 32 tables: tb<16 -> A strip (dl=tb&7, dq=tb>>3);
    //                 tb>=16 -> B strip (dc, dqy) likewise
    if (tid < 768) {
        int tb = tid / 24, e = tid % 24;
        int sIdx;
        const unsigned* src;
        if (tb < 16) { sIdx = (y0 + (tb & 7)) * 64 + bx * 2 + (tb >> 3); src = g_tabA; }
        else { int b2 = tb - 16; sIdx = (x0 + (b2 & 7)) * 64 + by * 2 + (b2 >> 3); src = g_tabB; }
        ((uint4*)(tabs + tb * TS))[e] =
            __ldg((const uint4*)(src + (size_t)sIdx * TS) + e);
    }
    __syncthreads();

    ull base;
    {
        const char* gp = (const char*)g_accT + half * 512 + l * 16;
        asm("cvta.to.global.u64 %0, %1;" : "=l"(base) : "l"(gp));
    }
    float* reg = stage + half * (64 * 132);

    // ---- phase A: x-strip (line y0+dl, x = x0 + dq*4 + p) ----
    {
        int dl = t & 7, dq = t >> 3;
        ull acc[8];
#pragma unroll
        for (int i = 0; i < 8; i++) acc[i] = 0ull;
        gather90(tabs + t * TS, base, acc);
        // stage A partials: local_px = (y-local)*8 + (x-local)
#pragma unroll
        for (int p = 0; p < 4; p++) {
            float* st = reg + (size_t)(dl * 8 + dq * 4 + p) * 132 + l * 4;
            *reinterpret_cast<float4*>(st) =
                make_float4(u64lo(acc[2 * p]),     u64hi(acc[2 * p]),
                            u64lo(acc[2 * p + 1]), u64hi(acc[2 * p + 1]));
        }
    }
    __syncthreads();

    // ---- phase B: y-strip (column x0+dc, y = y0 + dqy*4 + p) ----
    int dc = t & 7, dqy = t >> 3;
    ull acc[8];
#pragma unroll
    for (int p = 0; p < 4; p++) {           // init from A partials
        const float* st = reg + (size_t)((dqy * 4 + p) * 8 + dc) * 132 + l * 4;
        float4 q = *reinterpret_cast<const float4*>(st);
        acc[2 * p]     = pack2(q.x, q.y);
        acc[2 * p + 1] = pack2(q.z, q.w);
    }
    __syncthreads();                         // reads done before re-staging

    gather90(tabs + (16 + t) * TS, base, acc);

    __syncthreads();
#pragma unroll
    for (int p = 0; p < 4; p++) {            // stage final values
        float* st = reg + (size_t)((dqy * 4 + p) * 8 + dc) * 132 + l * 4;
        *reinterpret_cast<float4*>(st) =
            make_float4(u64lo(acc[2 * p]),     u64hi(acc[2 * p]),
                        u64lo(acc[2 * p + 1]), u64hi(acc[2 * p + 1]));
    }
    __syncthreads();

    // ---- epilogue: thread (c = tid&255, u = tid>>8) stores lines 2u, 2u+1 ----
    {
        int c = tid & 255, u = tid >> 8;
        int h2 = c >> 7, c2 = c & 127;
        const float* rg = stage + h2 * (64 * 132);
#pragma unroll
        for (int dl2 = 0; dl2 < 2; dl2++) {
            int LL = u * 2 + dl2;
            float* op = outp + (size_t)c * HW + (y0 + LL) * 256 + x0;
#pragma unroll
            for (int gg = 0; gg < 2; gg++) {
                int pb = LL * 8 + 4 * gg;
                float4 q = make_float4(rg[(size_t)(pb + 0) * 132 + c2],
                                       rg[(size_t)(pb + 1) * 132 + c2],
                                       rg[(size_t)(pb + 2) * 132 + c2],
                                       rg[(size_t)(pb + 3) * 132 + c2]);
                *reinterpret_cast<float4*>(op + 4 * gg) = q;
            }
        }
    }
}

extern "C" void kernel_launch(void* const* d_in, const int* in_sizes, int n_in,
                              void* d_out, int out_size) {
    const float* acc = (const float*)d_in[0];
    float* out = (float*)d_out;

    cudaFuncSetAttribute(k_fused, cudaFuncAttributeMaxDynamicSharedMemorySize,
                         SMEM_FUSED);

    k_trig<<<1, 192>>>();
    k_transpose<<<dim3(AR / 32, NC / 32), dim3(32, 8)>>>(acc);
    k_tab<<<dim3(NS4 / 8, 2), 256>>>();       // both sorted tables, one launch
    k_fused<<<1024, 1024, SMEM_FUSED>>>(out); // A + exchange + B + store
}